// round 3
// baseline (speedup 1.0000x reference)
#include <cuda_runtime.h>

// FCOS loss, GB300 sm_103a — single fused kernel (last-block finalize).
// Levels: HW = {12800, 3200, 800, 208, 56}, B=16, C=80.
// conf focal "neg" term streamed over all 21.84M conf elements (HBM-bound);
// positives-only work (IoU, centerness BCE, focal hit-correction) sparse.
// Input order (metadata = setup_inputs dict order), per level l:
//   d_in[6l+0]=conf, 6l+1=loc, 6l+2=center, 6l+3=ltrb, 6l+4=cls, 6l+5=pos

#define HW0 12800
#define HW1 3200
#define HW2 800
#define HW3 208
#define HW4 56

// per-batch conf segment sizes (80*HW)
#define S0 1024000
#define S1 256000
#define S2 64000
#define S3 16640
#define S4 4480

// conf blocks: 4096 elements per block (256 thr x 4 float4)
#define CB0 250
#define CB1 63
#define CB2 16
#define CB3 5
#define CB4 2
#define CCUM0 4000   // 250*16
#define CCUM1 5008   // +63*16
#define CCUM2 5264   // +16*16
#define CCUM3 5344   // +5*16
#define CCUM4 5376   // +2*16

// box blocks: 1024 pixels per block (256 thr x int4)
#define BB0 13
#define BB1 4
#define BCUM0 208    // 13*16
#define BCUM1 272    // +4*16
#define BCUM2 288    // +1*16
#define BCUM3 304
#define BCUM4 320

#define GRID_TOTAL (CCUM4 + BCUM4)   // 5696

__device__ double   g_conf[16];
__device__ double   g_l[16];
__device__ double   g_center[16];
__device__ int      g_pos[16];
__device__ unsigned g_done = 0;

__device__ __forceinline__ float neg_term(float p) {
    p = fminf(fmaxf(p, 1e-8f), 1.0f);
    return 0.75f * p * p * (-__logf(1.0f - p));
}

struct AllPtrs {
    const float* conf[5];
    const float* loc[5];
    const float* center[5];
    const float* ltrb[5];
    const int*   cls[5];
    const int*   pos[5];
};

// ---------------- sparse per-pixel work (positives only) ----------------

template <int HW>
__device__ __forceinline__ void box_work(
    const float* __restrict__ conf, const float* __restrict__ loc,
    const float* __restrict__ center, const float* __restrict__ ltrb,
    const int* __restrict__ cls, const int* __restrict__ pos,
    int b, int chunk, float& s_l, float& s_c, float& s_cf, int& cnt)
{
    const int pix0 = chunk * 1024 + (threadIdx.x << 2);
    if (pix0 >= HW) return;
    const int boff = b * HW;
    int4 pv = *reinterpret_cast<const int4*>(pos + boff + pix0);
    int pvA[4] = { pv.x, pv.y, pv.z, pv.w };
#pragma unroll
    for (int j = 0; j < 4; j++) {
        if (pvA[j] != 0) continue;
        int pix = pix0 + j;
        cnt++;
        float lt = ltrb[(b * 4 + 0) * HW + pix] * 32.0f;
        float tt = ltrb[(b * 4 + 1) * HW + pix] * 32.0f;
        float rt = ltrb[(b * 4 + 2) * HW + pix] * 32.0f;
        float bt = ltrb[(b * 4 + 3) * HW + pix] * 32.0f;
        float lp = loc[(b * 4 + 0) * HW + pix] * 32.0f;
        float tp = loc[(b * 4 + 1) * HW + pix] * 32.0f;
        float rp = loc[(b * 4 + 2) * HW + pix] * 32.0f;
        float bp = loc[(b * 4 + 3) * HW + pix] * 32.0f;

        float iw = fmaxf(fminf(lp, lt) + fminf(rp, rt), 0.0f);
        float ih = fmaxf(fminf(tp, tt) + fminf(bp, bt), 0.0f);
        float inter = iw * ih;
        float area_p = fmaxf(lp + rp, 0.0f) * fmaxf(tp + bp, 0.0f);
        float area_t = (lt + rt) * (tt + bt);
        float iou = inter / (area_p + area_t - inter + 1e-6f);
        s_l += -__logf(iou + 1e-6f);

        float ctr = sqrtf((fminf(lt, rt) / (fmaxf(lt, rt) + 1e-6f)) *
                          (fminf(tt, bt) / (fmaxf(tt, bt) + 1e-6f)));
        float cp = center[boff + pix];
        cp = fminf(fmaxf(cp, 1e-8f), 1.0f - 1e-8f);
        s_c += -(ctr * __logf(cp) + (1.0f - ctr) * __logf(1.0f - cp));

        int cv = cls[boff + pix];
        float p = conf[(b * 80 + cv) * HW + pix];
        p = fminf(fmaxf(p, 1e-8f), 1.0f);
        float posT = -0.25f * (1.0f - p) * (1.0f - p) * __logf(p);
        float negT = 0.75f * p * p * (-__logf(1.0f - p));
        s_cf += posT - negT;   // replace neg with pos at the hit channel
    }
}

// ---------------- fused kernel ----------------

__global__ __launch_bounds__(256) void fused_kernel(AllPtrs P, float* __restrict__ out)
{
    int bid = blockIdx.x;
    float s_l = 0.0f, s_c = 0.0f, s_cf = 0.0f;
    int cnt = 0;
    int b = 0;

    if (bid < CCUM4) {
        // ----- conf streaming block -----
        const float* base; int S, chunk;
        if (bid < CCUM0)      { b = bid / CB0; chunk = bid - b * CB0; base = P.conf[0] + b * S0; S = S0; }
        else if (bid < CCUM1) { int r = bid - CCUM0; b = r / CB1; chunk = r - b * CB1; base = P.conf[1] + b * S1; S = S1; }
        else if (bid < CCUM2) { int r = bid - CCUM1; b = r >> 4;  chunk = r & 15;      base = P.conf[2] + b * S2; S = S2; }
        else if (bid < CCUM3) { int r = bid - CCUM2; b = r / CB3; chunk = r - b * CB3; base = P.conf[3] + b * S3; S = S3; }
        else                  { int r = bid - CCUM3; b = r >> 1;  chunk = r & 1;       base = P.conf[4] + b * S4; S = S4; }

        int off = chunk * 4096 + (threadIdx.x << 2);
#pragma unroll
        for (int u = 0; u < 4; u++) {
            int i = off + u * 1024;
            if (i < S) {   // S and i multiples of 4 -> full float4 in-bounds
                float4 v = *reinterpret_cast<const float4*>(base + i);
                s_cf += neg_term(v.x) + neg_term(v.y) + neg_term(v.z) + neg_term(v.w);
            }
        }
    } else {
        // ----- sparse box block -----
        int rb = bid - CCUM4;
        if (rb < BCUM0) {
            b = rb / BB0; int chunk = rb - b * BB0;
            box_work<HW0>(P.conf[0], P.loc[0], P.center[0], P.ltrb[0], P.cls[0], P.pos[0], b, chunk, s_l, s_c, s_cf, cnt);
        } else if (rb < BCUM1) {
            int r = rb - BCUM0; b = r >> 2; int chunk = r & 3;
            box_work<HW1>(P.conf[1], P.loc[1], P.center[1], P.ltrb[1], P.cls[1], P.pos[1], b, chunk, s_l, s_c, s_cf, cnt);
        } else if (rb < BCUM2) {
            b = rb - BCUM1;
            box_work<HW2>(P.conf[2], P.loc[2], P.center[2], P.ltrb[2], P.cls[2], P.pos[2], b, 0, s_l, s_c, s_cf, cnt);
        } else if (rb < BCUM3) {
            b = rb - BCUM2;
            box_work<HW3>(P.conf[3], P.loc[3], P.center[3], P.ltrb[3], P.cls[3], P.pos[3], b, 0, s_l, s_c, s_cf, cnt);
        } else {
            b = rb - BCUM3;
            box_work<HW4>(P.conf[4], P.loc[4], P.center[4], P.ltrb[4], P.cls[4], P.pos[4], b, 0, s_l, s_c, s_cf, cnt);
        }
    }

    // ----- block reduce (3 floats + 1 int) -----
    __shared__ float shf[24];
    __shared__ int   shi[8];
#pragma unroll
    for (int o = 16; o > 0; o >>= 1) {
        s_l  += __shfl_down_sync(0xffffffffu, s_l,  o);
        s_c  += __shfl_down_sync(0xffffffffu, s_c,  o);
        s_cf += __shfl_down_sync(0xffffffffu, s_cf, o);
        cnt  += __shfl_down_sync(0xffffffffu, cnt,  o);
    }
    int w = threadIdx.x >> 5, l = threadIdx.x & 31;
    if (l == 0) { shf[w] = s_l; shf[8 + w] = s_c; shf[16 + w] = s_cf; shi[w] = cnt; }
    __syncthreads();

    if (threadIdx.x == 0) {
        float tl = 0.0f, tc = 0.0f, tcf = 0.0f; int tn = 0;
#pragma unroll
        for (int i = 0; i < 8; i++) { tl += shf[i]; tc += shf[8 + i]; tcf += shf[16 + i]; tn += shi[i]; }
        if (tl != 0.0f)  atomicAdd(&g_l[b], (double)tl);
        if (tc != 0.0f)  atomicAdd(&g_center[b], (double)tc);
        if (tcf != 0.0f) atomicAdd(&g_conf[b], (double)tcf);
        if (tn != 0)     atomicAdd(&g_pos[b], tn);
    }

    // ----- last-block finalize -----
    __shared__ unsigned is_last;
    __threadfence();
    if (threadIdx.x == 0)
        is_last = (atomicAdd(&g_done, 1u) == (unsigned)(GRID_TOTAL - 1)) ? 1u : 0u;
    __syncthreads();
    if (!is_last) return;

    __threadfence();   // acquire: all other blocks' accumulator writes visible

    if (threadIdx.x < 32) {
        int t = threadIdx.x;
        double v = 0.0;
        if (t < 16) {
            double lc   = *(volatile double*)&g_conf[t];
            double ll   = *(volatile double*)&g_l[t];
            double lctr = *(volatile double*)&g_center[t];
            int    n    = *(volatile int*)&g_pos[t];
            if (n > 0) v = lctr + (lc + ll) / (double)n;
            else       v = lctr + lc + ll;
            // reset state for next graph replay
            g_conf[t] = 0.0; g_l[t] = 0.0; g_center[t] = 0.0; g_pos[t] = 0;
        }
#pragma unroll
        for (int o = 8; o > 0; o >>= 1) v += __shfl_down_sync(0xffffffffu, v, o);
        if (t == 0) { out[0] = (float)(v / 16.0); g_done = 0; }
    }
}

extern "C" void kernel_launch(void* const* d_in, const int* in_sizes, int n_in,
                              void* d_out, int out_size)
{
    (void)out_size;
    AllPtrs P;

    // Level-grouped (setup_inputs dict order): in_sizes[1] = loc0 = 819200.
    // Type-grouped fallback: in_sizes[1] = conf1 = 4096000.
    bool level_grouped = (n_in >= 2 && in_sizes[1] == 819200);

    for (int l = 0; l < 5; l++) {
        int ic, ilo, ice, ilt, icl, ipo;
        if (level_grouped) {
            ic = 6 * l + 0; ilo = 6 * l + 1; ice = 6 * l + 2;
            ilt = 6 * l + 3; icl = 6 * l + 4; ipo = 6 * l + 5;
        } else {
            ic = l; ilo = 5 + l; ice = 10 + l; ilt = 15 + l; icl = 20 + l; ipo = 25 + l;
        }
        P.conf[l]   = (const float*)d_in[ic];
        P.loc[l]    = (const float*)d_in[ilo];
        P.center[l] = (const float*)d_in[ice];
        P.ltrb[l]   = (const float*)d_in[ilt];
        P.cls[l]    = (const int*)d_in[icl];
        P.pos[l]    = (const int*)d_in[ipo];
    }

    fused_kernel<<<GRID_TOTAL, 256>>>(P, (float*)d_out);
}

// round 4
// speedup vs baseline: 1.5220x; 1.5220x over previous
#include <cuda_runtime.h>

// FCOS loss, GB300 sm_103a — single fused kernel, last-block finalize.
// Levels: HW = {12800, 3200, 800, 208, 56}, B=16, C=80.
// Grid layout: [0,320) sparse box blocks (run first, overlap with stream),
//              [320, 3024) conf focal-neg streaming blocks (8192 elems each).
// Input order (metadata = setup_inputs dict order), per level l:
//   d_in[6l+0]=conf, 6l+1=loc, 6l+2=center, 6l+3=ltrb, 6l+4=cls, 6l+5=pos

#define HW0 12800
#define HW1 3200
#define HW2 800
#define HW3 208
#define HW4 56

// per-batch conf segment sizes (80*HW)
#define S0 1024000
#define S1 256000
#define S2 64000
#define S3 16640
#define S4 4480

// conf blocks: 8192 elements per block (256 thr x 8 float4), ceil(S/8192) per batch
#define CB0 125
#define CB1 32
#define CB2 8
#define CB3 3
#define CB4 1
#define CCUM0 2000   // 125*16
#define CCUM1 2512   // +32*16
#define CCUM2 2640   // +8*16
#define CCUM3 2688   // +3*16
#define CCUM4 2704   // +1*16

// box blocks: 1024 pixels per block (256 thr x int4)
#define BB0 13
#define BB1 4
#define BCUM0 208    // 13*16
#define BCUM1 272    // +4*16
#define BCUM2 288    // +1*16
#define BCUM3 304
#define BCUM4 320

#define GRID_TOTAL (BCUM4 + CCUM4)   // 3024

__device__ double   g_conf[16];
__device__ double   g_l[16];
__device__ double   g_center[16];
__device__ int      g_pos[16];
__device__ unsigned g_done = 0;

__device__ __forceinline__ float neg_term(float p) {
    p = fminf(fmaxf(p, 1e-8f), 1.0f);
    return 0.75f * p * p * (-__logf(1.0f - p));
}

struct AllPtrs {
    const float* conf[5];
    const float* loc[5];
    const float* center[5];
    const float* ltrb[5];
    const int*   cls[5];
    const int*   pos[5];
};

// ---------------- sparse per-pixel work (positives only) ----------------

template <int HW>
__device__ __forceinline__ void box_work(
    const float* __restrict__ conf, const float* __restrict__ loc,
    const float* __restrict__ center, const float* __restrict__ ltrb,
    const int* __restrict__ cls, const int* __restrict__ pos,
    int b, int chunk, float& s_l, float& s_c, float& s_cf, int& cnt)
{
    const int pix0 = chunk * 1024 + (threadIdx.x << 2);
    if (pix0 >= HW) return;
    const int boff = b * HW;
    int4 pv = *reinterpret_cast<const int4*>(pos + boff + pix0);
    int pvA[4] = { pv.x, pv.y, pv.z, pv.w };
#pragma unroll
    for (int j = 0; j < 4; j++) {
        if (pvA[j] != 0) continue;
        int pix = pix0 + j;
        cnt++;
        float lt = ltrb[(b * 4 + 0) * HW + pix] * 32.0f;
        float tt = ltrb[(b * 4 + 1) * HW + pix] * 32.0f;
        float rt = ltrb[(b * 4 + 2) * HW + pix] * 32.0f;
        float bt = ltrb[(b * 4 + 3) * HW + pix] * 32.0f;
        float lp = loc[(b * 4 + 0) * HW + pix] * 32.0f;
        float tp = loc[(b * 4 + 1) * HW + pix] * 32.0f;
        float rp = loc[(b * 4 + 2) * HW + pix] * 32.0f;
        float bp = loc[(b * 4 + 3) * HW + pix] * 32.0f;

        float iw = fmaxf(fminf(lp, lt) + fminf(rp, rt), 0.0f);
        float ih = fmaxf(fminf(tp, tt) + fminf(bp, bt), 0.0f);
        float inter = iw * ih;
        float area_p = fmaxf(lp + rp, 0.0f) * fmaxf(tp + bp, 0.0f);
        float area_t = (lt + rt) * (tt + bt);
        float iou = inter / (area_p + area_t - inter + 1e-6f);
        s_l += -__logf(iou + 1e-6f);

        float ctr = sqrtf((fminf(lt, rt) / (fmaxf(lt, rt) + 1e-6f)) *
                          (fminf(tt, bt) / (fmaxf(tt, bt) + 1e-6f)));
        float cp = center[boff + pix];
        cp = fminf(fmaxf(cp, 1e-8f), 1.0f - 1e-8f);
        s_c += -(ctr * __logf(cp) + (1.0f - ctr) * __logf(1.0f - cp));

        int cv = cls[boff + pix];
        float p = conf[(b * 80 + cv) * HW + pix];
        p = fminf(fmaxf(p, 1e-8f), 1.0f);
        float posT = -0.25f * (1.0f - p) * (1.0f - p) * __logf(p);
        float negT = 0.75f * p * p * (-__logf(1.0f - p));
        s_cf += posT - negT;   // replace neg with pos at the hit channel
    }
}

// ---------------- fused kernel ----------------

__global__ void __launch_bounds__(256, 8) fused_kernel(AllPtrs P, float* __restrict__ out)
{
    int bid = blockIdx.x;
    float s_l = 0.0f, s_c = 0.0f, s_cf = 0.0f;
    int cnt = 0;
    int b = 0;

    if (bid >= BCUM4) {
        // ----- conf streaming block -----
        int cb = bid - BCUM4;
        const float* base; int S, chunk;
        if (cb < CCUM0)      { b = cb / CB0; chunk = cb - b * CB0; base = P.conf[0] + b * S0; S = S0; }
        else if (cb < CCUM1) { int r = cb - CCUM0; b = r >> 5; chunk = r & 31; base = P.conf[1] + b * S1; S = S1; }
        else if (cb < CCUM2) { int r = cb - CCUM1; b = r >> 3; chunk = r & 7;  base = P.conf[2] + b * S2; S = S2; }
        else if (cb < CCUM3) { int r = cb - CCUM2; b = r / 3;  chunk = r - b * 3; base = P.conf[3] + b * S3; S = S3; }
        else                 { b = cb - CCUM3; chunk = 0; base = P.conf[4] + b * S4; S = S4; }

        int off = chunk * 8192 + (threadIdx.x << 2);
        float a0 = 0.0f, a1 = 0.0f;
#pragma unroll
        for (int u = 0; u < 8; u++) {
            int i = off + u * 1024;
            if (i < S) {   // S and i multiples of 4 -> full float4 in-bounds
                float4 v = *reinterpret_cast<const float4*>(base + i);
                a0 += neg_term(v.x) + neg_term(v.y);
                a1 += neg_term(v.z) + neg_term(v.w);
            }
        }
        s_cf = a0 + a1;
    } else {
        // ----- sparse box block (scheduled first to overlap with stream) -----
        int rb = bid;
        if (rb < BCUM0) {
            b = rb / BB0; int chunk = rb - b * BB0;
            box_work<HW0>(P.conf[0], P.loc[0], P.center[0], P.ltrb[0], P.cls[0], P.pos[0], b, chunk, s_l, s_c, s_cf, cnt);
        } else if (rb < BCUM1) {
            int r = rb - BCUM0; b = r >> 2; int chunk = r & 3;
            box_work<HW1>(P.conf[1], P.loc[1], P.center[1], P.ltrb[1], P.cls[1], P.pos[1], b, chunk, s_l, s_c, s_cf, cnt);
        } else if (rb < BCUM2) {
            b = rb - BCUM1;
            box_work<HW2>(P.conf[2], P.loc[2], P.center[2], P.ltrb[2], P.cls[2], P.pos[2], b, 0, s_l, s_c, s_cf, cnt);
        } else if (rb < BCUM3) {
            b = rb - BCUM2;
            box_work<HW3>(P.conf[3], P.loc[3], P.center[3], P.ltrb[3], P.cls[3], P.pos[3], b, 0, s_l, s_c, s_cf, cnt);
        } else {
            b = rb - BCUM3;
            box_work<HW4>(P.conf[4], P.loc[4], P.center[4], P.ltrb[4], P.cls[4], P.pos[4], b, 0, s_l, s_c, s_cf, cnt);
        }
    }

    // ----- block reduce (3 floats + 1 int) -----
    __shared__ float shf[24];
    __shared__ int   shi[8];
#pragma unroll
    for (int o = 16; o > 0; o >>= 1) {
        s_l  += __shfl_down_sync(0xffffffffu, s_l,  o);
        s_c  += __shfl_down_sync(0xffffffffu, s_c,  o);
        s_cf += __shfl_down_sync(0xffffffffu, s_cf, o);
        cnt  += __shfl_down_sync(0xffffffffu, cnt,  o);
    }
    int w = threadIdx.x >> 5, l = threadIdx.x & 31;
    if (l == 0) { shf[w] = s_l; shf[8 + w] = s_c; shf[16 + w] = s_cf; shi[w] = cnt; }
    __syncthreads();

    if (threadIdx.x == 0) {
        float tl = 0.0f, tc = 0.0f, tcf = 0.0f; int tn = 0;
#pragma unroll
        for (int i = 0; i < 8; i++) { tl += shf[i]; tc += shf[8 + i]; tcf += shf[16 + i]; tn += shi[i]; }
        if (tl != 0.0f)  atomicAdd(&g_l[b], (double)tl);
        if (tc != 0.0f)  atomicAdd(&g_center[b], (double)tc);
        if (tcf != 0.0f) atomicAdd(&g_conf[b], (double)tcf);
        if (tn != 0)     atomicAdd(&g_pos[b], tn);
    }

    // ----- last-block finalize -----
    __shared__ unsigned is_last;
    __threadfence();
    if (threadIdx.x == 0)
        is_last = (atomicAdd(&g_done, 1u) == (unsigned)(GRID_TOTAL - 1)) ? 1u : 0u;
    __syncthreads();
    if (!is_last) return;

    __threadfence();   // acquire: all other blocks' accumulator writes visible

    if (threadIdx.x < 32) {
        int t = threadIdx.x;
        double v = 0.0;
        if (t < 16) {
            double lc   = *(volatile double*)&g_conf[t];
            double ll   = *(volatile double*)&g_l[t];
            double lctr = *(volatile double*)&g_center[t];
            int    n    = *(volatile int*)&g_pos[t];
            if (n > 0) v = lctr + (lc + ll) / (double)n;
            else       v = lctr + lc + ll;
            // reset state for next graph replay
            g_conf[t] = 0.0; g_l[t] = 0.0; g_center[t] = 0.0; g_pos[t] = 0;
        }
#pragma unroll
        for (int o = 8; o > 0; o >>= 1) v += __shfl_down_sync(0xffffffffu, v, o);
        if (t == 0) { out[0] = (float)(v / 16.0); g_done = 0; }
    }
}

extern "C" void kernel_launch(void* const* d_in, const int* in_sizes, int n_in,
                              void* d_out, int out_size)
{
    (void)out_size;
    AllPtrs P;

    // Level-grouped (setup_inputs dict order): in_sizes[1] = loc0 = 819200.
    // Type-grouped fallback: in_sizes[1] = conf1 = 4096000.
    bool level_grouped = (n_in >= 2 && in_sizes[1] == 819200);

    for (int l = 0; l < 5; l++) {
        int ic, ilo, ice, ilt, icl, ipo;
        if (level_grouped) {
            ic = 6 * l + 0; ilo = 6 * l + 1; ice = 6 * l + 2;
            ilt = 6 * l + 3; icl = 6 * l + 4; ipo = 6 * l + 5;
        } else {
            ic = l; ilo = 5 + l; ice = 10 + l; ilt = 15 + l; icl = 20 + l; ipo = 25 + l;
        }
        P.conf[l]   = (const float*)d_in[ic];
        P.loc[l]    = (const float*)d_in[ilo];
        P.center[l] = (const float*)d_in[ice];
        P.ltrb[l]   = (const float*)d_in[ilt];
        P.cls[l]    = (const int*)d_in[icl];
        P.pos[l]    = (const int*)d_in[ipo];
    }

    fused_kernel<<<GRID_TOTAL, 256>>>(P, (float*)d_out);
}